// round 5
// baseline (speedup 1.0000x reference)
#include <cuda_runtime.h>
#include <cuda_fp16.h>
#include <cstdint>

// ---------------------------------------------------------------------------
// Problem constants
// ---------------------------------------------------------------------------
#define BATCH   8
#define TSTEPS  512
#define NEMBD   512
#define NHID    1024
#define VOCAB   32000
#define NROWS   (BATCH * TSTEPS)        // 4096
#define NG3     (3 * NHID)              // 3072

// GRU persistent kernel config
#define GRU_BLOCKS   128                // each owns 8 hidden columns
#define GRU_THREADS  512                // 16 warps
#define WK          1032                // row stride (halves) for weight rows

// GRU SMEM layout
#define WSM_BYTES   (24 * WK * 2)       // 49536  fp16 weights [gate*8+col][k]
#define PBUF_FLOATS (16 * 64)           // 1024   fp32 partials
#define XBUF_FLOATS 192
#define ZSM_FLOATS  64
#define HPSM_FLOATS 64
#define BSM_FLOATS  24
#define GRU_SMEM_BYTES (WSM_BYTES + (PBUF_FLOATS + XBUF_FLOATS + ZSM_FLOATS + HPSM_FLOATS + BSM_FLOATS) * 4)

// ---------------------------------------------------------------------------
// Device scratch (host resolves ONLY via cudaGetSymbolAddress)
// ---------------------------------------------------------------------------
__device__ __half              g_h16[BATCH * NHID];          // carry h (fp16)
__device__ __half              g_rh16[BATCH * NHID];         // r*h broadcast (fp16)
__device__ __half              g_hs[(size_t)NROWS * NHID];   // hidden states (fp16)
__device__ __half              g_wlm[(size_t)NHID * VOCAB];  // lm head weights fp16
__device__ __half              g_emb[(size_t)NROWS * NEMBD]; // gathered embeddings fp16
__device__ __half              g_wx[(size_t)NEMBD * NG3];    // x-part weights fp16
__device__ float               g_xp[(size_t)NROWS * NG3];    // precomputed x-projections
__device__ unsigned long long  g_ctrs[256];                  // barrier counters [0],[128]
__device__ float               g_logits_fb[(size_t)NROWS * VOCAB];

// ---------------------------------------------------------------------------
// Grid barrier: release-add + TIGHT acquire-poll (poll period self-limited to
// ~L2 latency by the load->branch dependency; no nanosleep overshoot).
// Cumulative ticket counter -> graph-replay-safe.
// ---------------------------------------------------------------------------
__device__ __forceinline__ void group_barrier(unsigned long long* ctr) {
    __syncthreads();
    if (threadIdx.x == 0) {
        unsigned long long one = 1ULL, old;
        asm volatile("atom.add.release.gpu.global.u64 %0, [%1], %2;"
                     : "=l"(old) : "l"(ctr), "l"(one) : "memory");
        unsigned long long target = ((old + 1ULL + (GRU_BLOCKS - 1)) / GRU_BLOCKS) * GRU_BLOCKS;
        unsigned long long cur;
        do {
            asm volatile("ld.acquire.gpu.global.u64 %0, [%1];"
                         : "=l"(cur) : "l"(ctr) : "memory");
        } while (cur < target);
    }
    __syncthreads();
}

// ---------------------------------------------------------------------------
// mma m16n8k16 f16 -> f32
// ---------------------------------------------------------------------------
__device__ __forceinline__ void mma16816(float& c0, float& c1, float& c2, float& c3,
                                         unsigned a0, unsigned a1, unsigned a2, unsigned a3,
                                         unsigned b0, unsigned b1) {
    asm volatile(
        "mma.sync.aligned.m16n8k16.row.col.f32.f16.f16.f32 "
        "{%0,%1,%2,%3}, {%4,%5,%6,%7}, {%8,%9}, {%0,%1,%2,%3};\n"
        : "+f"(c0), "+f"(c1), "+f"(c2), "+f"(c3)
        : "r"(a0), "r"(a1), "r"(a2), "r"(a3), "r"(b0), "r"(b1));
}

// ---------------------------------------------------------------------------
// Persistent GRU scan. Block owns hidden cols [colbase, colbase+8).
// A-fragments loaded DIRECTLY from global (no SMEM staging: zero reuse).
// Phase A: warps 0-7 -> z (K slice 128 each), warps 8-15 -> r.
// Phase B: all 16 warps -> hbar (K slice 64 each).
// ---------------------------------------------------------------------------
__global__ void __launch_bounds__(GRU_THREADS, 1)
gru_kernel(const float* __restrict__ start,
           const float* __restrict__ Wz, const float* __restrict__ bz,
           const float* __restrict__ Wr, const float* __restrict__ br,
           const float* __restrict__ Wh, const float* __restrict__ bh) {
    extern __shared__ char smem[];
    __half* wsm  = (__half*)smem;                  // [24][WK]
    float*  pbuf = (float*)(smem + WSM_BYTES);     // [16][64]
    float*  xbuf = pbuf + PBUF_FLOATS;             // [192]
    float*  zsm  = xbuf + XBUF_FLOATS;             // [64]
    float*  hpsm = zsm + ZSM_FLOATS;               // [64] fp32 carried h (owned cols)
    float*  bsm  = hpsm + HPSM_FLOATS;             // [24]

    const int tid     = threadIdx.x;
    const int warp    = tid >> 5;
    const int lane    = tid & 31;
    const int colbase = blockIdx.x * 8;

    // --- init: weights, biases, carried h, and global h16 slice ---
    for (int i = tid; i < 24 * 1024; i += GRU_THREADS) {
        int j = i >> 10, k = i & 1023;             // j = gate*8+col
        int g = j >> 3;
        const float* W = (g == 0) ? Wz : ((g == 1) ? Wr : Wh);
        wsm[j * WK + k] = __float2half(W[(size_t)(NEMBD + k) * NHID + colbase + (j & 7)]);
    }
    if (tid < 24) bsm[tid] = (tid < 8 ? bz[colbase + tid]
                              : tid < 16 ? br[colbase + tid - 8]
                                         : bh[colbase + tid - 16]);
    if (tid < 64) {
        int b = tid >> 3, j = tid & 7;
        float sv = start[colbase + j];
        hpsm[tid] = sv;
        g_h16[b * NHID + colbase + j] = __float2half(sv);
    }
    group_barrier(&g_ctrs[0]);   // g_h16 fully initialized chip-wide

    const int xb   = tid / 24;                  // tid<192: batch
    const int xrem = tid - xb * 24;             // gate*8+j

    const int frow = lane >> 2;                 // m (batch row) / n (col) in frags
    const int fk   = (lane & 3) * 2;            // k pair

    // phase A addressing (per warp)
    const int gA   = warp >> 3;                 // 0:z 1:r
    const int kbA  = (warp & 7) * 128;
    const __half* wrowA = wsm + (gA * 8 + frow) * WK;
    // phase B addressing
    const int kbB  = warp * 64;
    const __half* wrowB = wsm + (16 + frow) * WK;

    for (int t = 0; t < TSTEPS; ++t) {
        // prefetch Xproj for this step (consumed at reduce time)
        float xpre = 0.f;
        if (tid < 192)
            xpre = g_xp[((size_t)(xb * TSTEPS + t)) * NG3 + (xrem >> 3) * NHID + colbase + (xrem & 7)];

        // ---- Phase A: z or r, direct-LDG fragments ----
        {
            float c0 = 0.f, c1 = 0.f, c2 = 0.f, c3 = 0.f;
#pragma unroll
            for (int c = 0; c < 8; c++) {
                int k0 = kbA + c * 16;
                unsigned a0 = *(const unsigned*)&g_h16[frow * NHID + k0 + fk];
                unsigned a2 = *(const unsigned*)&g_h16[frow * NHID + k0 + 8 + fk];
                unsigned b0 = *(const unsigned*)&wrowA[k0 + fk];
                unsigned b1 = *(const unsigned*)&wrowA[k0 + 8 + fk];
                mma16816(c0, c1, c2, c3, a0, 0u, a2, 0u, b0, b1);
            }
            pbuf[(gA * 8 + (warp & 7)) * 64 + frow * 8 + fk]     = c0;
            pbuf[(gA * 8 + (warp & 7)) * 64 + frow * 8 + fk + 1] = c1;
        }
        if (tid < 192) xbuf[tid] = xpre;
        __syncthreads();

        // reduce + activations (z -> zsm, r -> r*h to global)
        if (tid < 128) {
            int b = tid >> 4, jj = tid & 15;
            int g = jj >> 3, j = jj & 7;
            float s = 0.f;
#pragma unroll
            for (int w = 0; w < 8; w++) s += pbuf[(g * 8 + w) * 64 + b * 8 + j];
            if (g == 0) {
                float z = 1.f / (1.f + __expf(-(s + xbuf[b * 24 + j] + bsm[j])));
                zsm[b * 8 + j] = z;
            } else {
                float r = 1.f / (1.f + __expf(-(s + xbuf[b * 24 + 8 + j] + bsm[8 + j])));
                g_rh16[b * NHID + colbase + j] = __float2half(r * hpsm[b * 8 + j]);
            }
        }
        group_barrier(&g_ctrs[0]);

        // ---- Phase B: hbar, direct-LDG fragments from r*h ----
        {
            float c0 = 0.f, c1 = 0.f, c2 = 0.f, c3 = 0.f;
#pragma unroll
            for (int c = 0; c < 4; c++) {
                int k0 = kbB + c * 16;
                unsigned a0 = *(const unsigned*)&g_rh16[frow * NHID + k0 + fk];
                unsigned a2 = *(const unsigned*)&g_rh16[frow * NHID + k0 + 8 + fk];
                unsigned b0 = *(const unsigned*)&wrowB[k0 + fk];
                unsigned b1 = *(const unsigned*)&wrowB[k0 + 8 + fk];
                mma16816(c0, c1, c2, c3, a0, 0u, a2, 0u, b0, b1);
            }
            pbuf[warp * 64 + frow * 8 + fk]     = c0;
            pbuf[warp * 64 + frow * 8 + fk + 1] = c1;
        }
        __syncthreads();

        if (tid < 64) {
            int b = tid >> 3, j = tid & 7;
            float s = 0.f;
#pragma unroll
            for (int w = 0; w < 16; w++) s += pbuf[w * 64 + b * 8 + j];
            float hbar  = tanhf(s + xbuf[b * 24 + 16 + j] + bsm[16 + j]);
            float hprev = hpsm[tid];
            float z     = zsm[tid];
            float hn    = hprev + z * (hbar - hprev);
            hpsm[tid] = hn;
            __half hh = __float2half(hn);
            int c = colbase + j;
            g_h16[b * NHID + c] = hh;
            g_hs[(size_t)(b * TSTEPS + t) * NHID + c] = hh;
        }
        group_barrier(&g_ctrs[128]);
    }
}

// ---------------------------------------------------------------------------
// Prep kernels
// ---------------------------------------------------------------------------
__global__ void cvt_half2(const float2* __restrict__ src, __half2* __restrict__ dst, int n2) {
    int i = blockIdx.x * blockDim.x + threadIdx.x;
    int stride = gridDim.x * blockDim.x;
    for (; i < n2; i += stride) {
        float2 v = src[i];
        dst[i] = __floats2half2_rn(v.x, v.y);
    }
}

__global__ void build_wx(const float* __restrict__ Wz, const float* __restrict__ Wr,
                         const float* __restrict__ Wh, __half* __restrict__ dst) {
    int i = blockIdx.x * blockDim.x + threadIdx.x;
    if (i >= NEMBD * NG3) return;
    int k = i / NG3, c = i - k * NG3;
    int g = c >> 10, j = c & 1023;
    const float* W = (g == 0) ? Wz : ((g == 1) ? Wr : Wh);
    dst[i] = __float2half(W[(size_t)k * NHID + j]);
}

__global__ void gather_emb(const int* __restrict__ idx, const float* __restrict__ wte,
                           __half* __restrict__ dst) {
    int r = blockIdx.x;
    int tok = idx[r];
    float4 v = ((const float4*)(wte + (size_t)tok * NEMBD))[threadIdx.x];
    __half2* d = (__half2*)(dst + (size_t)r * NEMBD);
    d[threadIdx.x * 2]     = __floats2half2_rn(v.x, v.y);
    d[threadIdx.x * 2 + 1] = __floats2half2_rn(v.z, v.w);
}

// ---------------------------------------------------------------------------
// fp16 tensor-core GEMM: C[M,NCOLS] = A[M,KDIM] * B[KDIM,NCOLS] (+bias)
// ---------------------------------------------------------------------------
#define AS_STRIDE 40
#define BS_STRIDE 42

template<int KDIM, int NCOLS, bool HAS_BIAS>
__global__ void __launch_bounds__(256)
gemm_kernel(const __half* __restrict__ A, const __half* __restrict__ Bw,
            const float* __restrict__ bias, float* __restrict__ C) {
    const int bx = blockIdx.x, by = blockIdx.y;
    const int tid = threadIdx.x, warp = tid >> 5, lane = tid & 31;
    const int wm = warp >> 2, wn = warp & 3;
    __shared__ __half As[128 * AS_STRIDE];
    __shared__ __half Bs[128 * BS_STRIDE];

    float acc[4][4][4];
#pragma unroll
    for (int a = 0; a < 4; a++)
#pragma unroll
        for (int b = 0; b < 4; b++)
#pragma unroll
            for (int c = 0; c < 4; c++) acc[a][b][c] = 0.f;

    const int m0 = by * 128, n0 = bx * 128;

    for (int k0 = 0; k0 < KDIM; k0 += 32) {
#pragma unroll
        for (int i = tid; i < 512; i += 256) {
            int row = i >> 2, seg = i & 3;
            *(uint4*)&As[row * AS_STRIDE + seg * 8] =
                *(const uint4*)&A[(size_t)(m0 + row) * KDIM + k0 + seg * 8];
        }
#pragma unroll
        for (int i = tid; i < 2048; i += 256) {
            int k = i >> 6, np = i & 63;
            __half2 h2 = *(const __half2*)(Bw + (size_t)(k0 + k) * NCOLS + n0 + np * 2);
            Bs[(np * 2)     * BS_STRIDE + k] = __low2half(h2);
            Bs[(np * 2 + 1) * BS_STRIDE + k] = __high2half(h2);
        }
        __syncthreads();

#pragma unroll
        for (int kk = 0; kk < 2; kk++) {
            unsigned a[4][4], b[4][2];
            const int kc = kk * 16 + (lane & 3) * 2;
            const int r  = lane >> 2;
#pragma unroll
            for (int mt = 0; mt < 4; mt++) {
                int rr = wm * 64 + mt * 16 + r;
                a[mt][0] = *(const unsigned*)&As[rr * AS_STRIDE + kc];
                a[mt][1] = *(const unsigned*)&As[(rr + 8) * AS_STRIDE + kc];
                a[mt][2] = *(const unsigned*)&As[rr * AS_STRIDE + kc + 8];
                a[mt][3] = *(const unsigned*)&As[(rr + 8) * AS_STRIDE + kc + 8];
            }
#pragma unroll
            for (int nt = 0; nt < 4; nt++) {
                int nn = wn * 32 + nt * 8 + r;
                b[nt][0] = *(const unsigned*)&Bs[nn * BS_STRIDE + kc];
                b[nt][1] = *(const unsigned*)&Bs[nn * BS_STRIDE + kc + 8];
            }
#pragma unroll
            for (int mt = 0; mt < 4; mt++)
#pragma unroll
                for (int nt = 0; nt < 4; nt++)
                    mma16816(acc[mt][nt][0], acc[mt][nt][1], acc[mt][nt][2], acc[mt][nt][3],
                             a[mt][0], a[mt][1], a[mt][2], a[mt][3], b[nt][0], b[nt][1]);
        }
        __syncthreads();
    }

#pragma unroll
    for (int mt = 0; mt < 4; mt++) {
#pragma unroll
        for (int nt = 0; nt < 4; nt++) {
            int gr = m0 + wm * 64 + mt * 16 + (lane >> 2);
            int gc = n0 + wn * 32 + nt * 8 + (lane & 3) * 2;
            float b0 = 0.f, b1 = 0.f;
            if (HAS_BIAS) { b0 = bias[gc]; b1 = bias[gc + 1]; }
            float2 v0 = make_float2(acc[mt][nt][0] + b0, acc[mt][nt][1] + b1);
            float2 v1 = make_float2(acc[mt][nt][2] + b0, acc[mt][nt][3] + b1);
            *(float2*)&C[(size_t)gr * NCOLS + gc]       = v0;
            *(float2*)&C[(size_t)(gr + 8) * NCOLS + gc] = v1;
        }
    }
}

// ---------------------------------------------------------------------------
// Loss
// ---------------------------------------------------------------------------
__global__ void __launch_bounds__(256)
loss_kernel(const float* __restrict__ logits, const int* __restrict__ targets,
            float* __restrict__ out_loss) {
    const int row = blockIdx.x;
    const float* lr = logits + (size_t)row * VOCAB;
    const int tid = threadIdx.x;

    float m = -1e30f, s = 0.f;
    for (int i = tid; i < VOCAB; i += 256) {
        float v = lr[i];
        float nm = fmaxf(m, v);
        s = s * __expf(m - nm) + __expf(v - nm);
        m = nm;
    }
    __shared__ float sm_m[256], sm_s[256];
    sm_m[tid] = m; sm_s[tid] = s;
    __syncthreads();
    for (int off = 128; off > 0; off >>= 1) {
        if (tid < off) {
            float m2 = sm_m[tid + off], s2 = sm_s[tid + off];
            float m1 = sm_m[tid],       s1 = sm_s[tid];
            float nm = fmaxf(m1, m2);
            sm_s[tid] = s1 * __expf(m1 - nm) + s2 * __expf(m2 - nm);
            sm_m[tid] = nm;
        }
        __syncthreads();
    }
    if (tid == 0) {
        float lse = sm_m[0] + logf(sm_s[0]);
        float tl  = lr[targets[row]];
        atomicAdd(out_loss, (lse - tl) * (1.0f / (float)NROWS));
    }
}

// ---------------------------------------------------------------------------
// Host entry
// ---------------------------------------------------------------------------
extern "C" void kernel_launch(void* const* d_in, const int* in_sizes, int n_in,
                              void* d_out, int out_size) {
    const int*   idx   = (const int*)d_in[0];
    const int*   tgt   = (const int*)d_in[1];
    const float* wte   = (const float*)d_in[2];
    const float* start = (const float*)d_in[3];
    const float* Wz    = (const float*)d_in[4];
    const float* bz    = (const float*)d_in[5];
    const float* Wr    = (const float*)d_in[6];
    const float* br    = (const float*)d_in[7];
    const float* Wh    = (const float*)d_in[8];
    const float* bh    = (const float*)d_in[9];
    const float* lmW   = (const float*)d_in[10];
    const float* lmb   = (const float*)d_in[11];

    void *p_hs, *p_wlm, *p_fb, *p_emb, *p_wx, *p_xp;
    cudaGetSymbolAddress(&p_hs,  g_hs);
    cudaGetSymbolAddress(&p_wlm, g_wlm);
    cudaGetSymbolAddress(&p_fb,  g_logits_fb);
    cudaGetSymbolAddress(&p_emb, g_emb);
    cudaGetSymbolAddress(&p_wx,  g_wx);
    cudaGetSymbolAddress(&p_xp,  g_xp);
    __half* d_hs  = (__half*)p_hs;
    __half* d_wlm = (__half*)p_wlm;
    float*  d_fb  = (float*)p_fb;
    __half* d_emb = (__half*)p_emb;
    __half* d_wx  = (__half*)p_wx;
    float*  d_xp  = (float*)p_xp;

    cudaFuncSetAttribute(gru_kernel, cudaFuncAttributeMaxDynamicSharedMemorySize,
                         GRU_SMEM_BYTES);

    build_wx<<<(NEMBD * NG3 + 255) / 256, 256>>>(Wz, Wr, Wh, d_wx);
    gather_emb<<<NROWS, 128>>>(idx, wte, d_emb);

    gemm_kernel<NEMBD, NG3, false><<<dim3(NG3 / 128, NROWS / 128), 256>>>(
        d_emb, d_wx, nullptr, d_xp);

    gru_kernel<<<GRU_BLOCKS, GRU_THREADS, GRU_SMEM_BYTES>>>(start, Wz, bz, Wr, br, Wh, bh);

    cvt_half2<<<4096, 256>>>((const float2*)lmW, (__half2*)d_wlm, (NHID * VOCAB) / 2);
    const long long NL = (long long)NROWS * VOCAB;
    float* fo = (float*)d_out;
    float* logits = ((long long)out_size >= NL) ? fo : d_fb;
    gemm_kernel<NHID, VOCAB, true><<<dim3(VOCAB / 128, NROWS / 128), 256>>>(
        d_hs, d_wlm, lmb, logits);

    float* loss_ptr = nullptr;
    if ((long long)out_size >= NL + 1)      loss_ptr = fo + NL;
    else if ((long long)out_size < NL)      loss_ptr = fo;
    if (loss_ptr) {
        cudaMemsetAsync(loss_ptr, 0, sizeof(float));
        loss_kernel<<<NROWS, 256>>>(logits, tgt, loss_ptr);
    }
}

// round 6
// speedup vs baseline: 1.0449x; 1.0449x over previous
#include <cuda_runtime.h>
#include <cuda_fp16.h>
#include <cstdint>

// ---------------------------------------------------------------------------
// Problem constants
// ---------------------------------------------------------------------------
#define BATCH   8
#define TSTEPS  512
#define NEMBD   512
#define NHID    1024
#define VOCAB   32000
#define NROWS   (BATCH * TSTEPS)        // 4096
#define NG3     (3 * NHID)              // 3072

// GRU persistent kernel config: 64 blocks x 16 columns
#define GRU_BLOCKS   64
#define GRU_THREADS  512                // 16 warps
#define NCOL         16                 // hidden columns per block
#define WK           1032               // row stride in halves (bank-spread pad)

// GRU SMEM layout
#define WSM_BYTES   (48 * WK * 2)       // 99072  fp16 weights [gate*16+col][k]
#define HSM_BYTES   (8 * WK * 2)        // 16512  fp16 staged h / r*h
#define PBUF_FLOATS (16 * 64)           // 1024
#define XBUF_FLOATS 384                 // [8][48]
#define ZSM_FLOATS  128                 // [8][16]
#define HPSM_FLOATS 128                 // [8][16]
#define BSM_FLOATS  48
#define GRU_SMEM_BYTES (WSM_BYTES + HSM_BYTES + \
    (PBUF_FLOATS + XBUF_FLOATS + ZSM_FLOATS + HPSM_FLOATS + BSM_FLOATS) * 4)

// ---------------------------------------------------------------------------
// Device scratch (host resolves ONLY via cudaGetSymbolAddress)
// ---------------------------------------------------------------------------
__device__ __half              g_h16[BATCH * NHID];          // carry h (fp16)
__device__ __half              g_rh16[BATCH * NHID];         // r*h broadcast (fp16)
__device__ __half              g_hs[(size_t)NROWS * NHID];   // hidden states (fp16)
__device__ __half              g_wlm[(size_t)NHID * VOCAB];  // lm head weights fp16
__device__ __half              g_emb[(size_t)NROWS * NEMBD]; // gathered embeddings fp16
__device__ __half              g_wx[(size_t)NEMBD * NG3];    // x-part weights fp16
__device__ float               g_xp[(size_t)NROWS * NG3];    // precomputed x-projections
__device__ unsigned long long  g_ctrs[256];                  // barrier counters [0],[128]
__device__ float               g_logits_fb[(size_t)NROWS * VOCAB];

// ---------------------------------------------------------------------------
// Grid barrier (R4 mechanism): release-add + acquire-poll with nanosleep
// backoff. Cumulative ticket counter -> graph-replay-safe.
// ---------------------------------------------------------------------------
__device__ __forceinline__ void group_barrier(unsigned long long* ctr) {
    __syncthreads();
    if (threadIdx.x == 0) {
        unsigned long long one = 1ULL, old;
        asm volatile("atom.add.release.gpu.global.u64 %0, [%1], %2;"
                     : "=l"(old) : "l"(ctr), "l"(one) : "memory");
        unsigned long long target = ((old + 1ULL + (GRU_BLOCKS - 1)) / GRU_BLOCKS) * GRU_BLOCKS;
        unsigned long long cur;
        asm volatile("ld.acquire.gpu.global.u64 %0, [%1];" : "=l"(cur) : "l"(ctr) : "memory");
        while (cur < target) {
            __nanosleep(64);
            asm volatile("ld.acquire.gpu.global.u64 %0, [%1];" : "=l"(cur) : "l"(ctr) : "memory");
        }
    }
    __syncthreads();
}

// ---------------------------------------------------------------------------
// mma m16n8k16 f16 -> f32
// ---------------------------------------------------------------------------
__device__ __forceinline__ void mma16816(float& c0, float& c1, float& c2, float& c3,
                                         unsigned a0, unsigned a1, unsigned a2, unsigned a3,
                                         unsigned b0, unsigned b1) {
    asm volatile(
        "mma.sync.aligned.m16n8k16.row.col.f32.f16.f16.f32 "
        "{%0,%1,%2,%3}, {%4,%5,%6,%7}, {%8,%9}, {%0,%1,%2,%3};\n"
        : "+f"(c0), "+f"(c1), "+f"(c2), "+f"(c3)
        : "r"(a0), "r"(a1), "r"(a2), "r"(a3), "r"(b0), "r"(b1));
}

// ---------------------------------------------------------------------------
// Persistent GRU scan. Block owns hidden cols [colbase, colbase+16).
// Phase A: warps 0-7 -> z, 8-15 -> r. Within a gate: colgroup = w&1 (8 cols),
//          kslice = (w>>1)&3 (K=256 each). 16 mmas/warp from SMEM.
// Phase B: colgroup = w&1, kslice = w>>1 (K=128 each). 8 mmas/warp.
// Batch rows 0-7 real; m16 rows 8-15 implicit zeros (a1=a3=0).
// ---------------------------------------------------------------------------
__global__ void __launch_bounds__(GRU_THREADS, 1)
gru_kernel(const float* __restrict__ start,
           const float* __restrict__ Wz, const float* __restrict__ bz,
           const float* __restrict__ Wr, const float* __restrict__ br,
           const float* __restrict__ Wh, const float* __restrict__ bh) {
    extern __shared__ char smem[];
    __half* wsm  = (__half*)smem;                          // [48][WK]
    __half* hsm  = (__half*)(smem + WSM_BYTES);            // [8][WK]
    float*  pbuf = (float*)(smem + WSM_BYTES + HSM_BYTES); // [16][64]
    float*  xbuf = pbuf + PBUF_FLOATS;                     // [8][48]
    float*  zsm  = xbuf + XBUF_FLOATS;                     // [8][16]
    float*  hpsm = zsm + ZSM_FLOATS;                       // [8][16] fp32 carried h
    float*  bsm  = hpsm + HPSM_FLOATS;                     // [48]

    const int tid     = threadIdx.x;
    const int warp    = tid >> 5;
    const int lane    = tid & 31;
    const int colbase = blockIdx.x * NCOL;

    // --- init: weights [gate*16+c][k], biases, carried h ---
    for (int i = tid; i < 48 * 1024; i += GRU_THREADS) {
        int j = i >> 10, k = i & 1023;             // j = gate*16+col
        int g = j >> 4;
        const float* W = (g == 0) ? Wz : ((g == 1) ? Wr : Wh);
        wsm[j * WK + k] = __float2half(W[(size_t)(NEMBD + k) * NHID + colbase + (j & 15)]);
    }
    if (tid < 48) {
        int g = tid >> 4, c = tid & 15;
        const float* B = (g == 0) ? bz : ((g == 1) ? br : bh);
        bsm[tid] = B[colbase + c];
    }
    if (tid < 128) hpsm[tid] = start[colbase + (tid & 15)];   // [b][c] broadcast

    const float4* start4 = (const float4*)start;
    const uint4*  h16v   = (const uint4*)g_h16;
    const uint4*  rh16v  = (const uint4*)g_rh16;

    // xbuf mapping for tid<384: b = tid/48, rem = tid%48 (= gate*16+c)
    const int xb   = tid / 48;
    const int xrem = tid - xb * 48;

    const int frow = lane >> 2;                 // batch row (m) / col (n) in frags
    const int fk   = (lane & 3) * 2;            // k pair

    // phase A addressing
    const int gA  = warp >> 3;                  // 0:z 1:r
    const int cgA = warp & 1;                   // colgroup (8 cols)
    const int ksA = (warp >> 1) & 3;            // K slice of 256
    const __half* wrowA = wsm + (gA * 16 + cgA * 8 + frow) * WK;
    // phase B addressing
    const int cgB = warp & 1;
    const int ksB = warp >> 1;                  // K slice of 128
    const __half* wrowB = wsm + (32 + cgB * 8 + frow) * WK;

    for (int t = 0; t < TSTEPS; ++t) {
        // prefetch Xproj for this step
        float xpre = 0.f;
        if (tid < 384)
            xpre = g_xp[((size_t)(xb * TSTEPS + t)) * NG3 + (xrem >> 4) * NHID + colbase + (xrem & 15)];

        // ---- stage h rows 0-7 (fp16) into SMEM ----
        if (t == 0) {
            for (int i = tid; i < 1024; i += GRU_THREADS) {
                int b = i >> 7, seg = i & 127;
                float4 v0 = start4[seg * 2], v1 = start4[seg * 2 + 1];
                __half2 h0 = __floats2half2_rn(v0.x, v0.y);
                __half2 h1 = __floats2half2_rn(v0.z, v0.w);
                __half2 h2 = __floats2half2_rn(v1.x, v1.y);
                __half2 h3 = __floats2half2_rn(v1.z, v1.w);
                uint4 u;
                u.x = *(unsigned*)&h0; u.y = *(unsigned*)&h1;
                u.z = *(unsigned*)&h2; u.w = *(unsigned*)&h3;
                *(uint4*)&hsm[b * WK + seg * 8] = u;
            }
        } else {
            for (int i = tid; i < 1024; i += GRU_THREADS) {
                int b = i >> 7, seg = i & 127;
                *(uint4*)&hsm[b * WK + seg * 8] = h16v[b * 128 + seg];
            }
        }
        __syncthreads();

        // ---- Phase A: z (warps 0-7) / r (warps 8-15) ----
        {
            float c0 = 0.f, c1 = 0.f, c2 = 0.f, c3 = 0.f;
            const int kb = ksA * 256;
#pragma unroll
            for (int c = 0; c < 16; c++) {
                int k0 = kb + c * 16;
                unsigned a0 = *(const unsigned*)&hsm[frow * WK + k0 + fk];
                unsigned a2 = *(const unsigned*)&hsm[frow * WK + k0 + 8 + fk];
                unsigned b0 = *(const unsigned*)&wrowA[k0 + fk];
                unsigned b1 = *(const unsigned*)&wrowA[k0 + 8 + fk];
                mma16816(c0, c1, c2, c3, a0, 0u, a2, 0u, b0, b1);
            }
            // pbuf set index: ((g*2+cg)*4 + ks)
            float* p = pbuf + ((gA * 2 + cgA) * 4 + ksA) * 64;
            p[frow * 8 + fk]     = c0;
            p[frow * 8 + fk + 1] = c1;
        }
        if (tid < 384) xbuf[tid] = xpre;
        __syncthreads();

        // reduce + activations: tid<256 -> (g, b, c)
        if (tid < 256) {
            int g = tid >> 7, rem = tid & 127;
            int b = rem >> 4, c = rem & 15;
            int cg = c >> 3, j = c & 7;
            float s = 0.f;
#pragma unroll
            for (int ks = 0; ks < 4; ks++)
                s += pbuf[((g * 2 + cg) * 4 + ks) * 64 + b * 8 + j];
            if (g == 0) {
                float z = 1.f / (1.f + __expf(-(s + xbuf[b * 48 + c] + bsm[c])));
                zsm[b * 16 + c] = z;
            } else {
                float r = 1.f / (1.f + __expf(-(s + xbuf[b * 48 + 16 + c] + bsm[16 + c])));
                g_rh16[b * NHID + colbase + c] = __float2half(r * hpsm[b * 16 + c]);
            }
        }
        group_barrier(&g_ctrs[0]);

        // ---- stage r*h ----
        for (int i = tid; i < 1024; i += GRU_THREADS) {
            int b = i >> 7, seg = i & 127;
            *(uint4*)&hsm[b * WK + seg * 8] = rh16v[b * 128 + seg];
        }
        __syncthreads();

        // ---- Phase B: hbar ----
        {
            float c0 = 0.f, c1 = 0.f, c2 = 0.f, c3 = 0.f;
            const int kb = ksB * 128;
#pragma unroll
            for (int c = 0; c < 8; c++) {
                int k0 = kb + c * 16;
                unsigned a0 = *(const unsigned*)&hsm[frow * WK + k0 + fk];
                unsigned a2 = *(const unsigned*)&hsm[frow * WK + k0 + 8 + fk];
                unsigned b0 = *(const unsigned*)&wrowB[k0 + fk];
                unsigned b1 = *(const unsigned*)&wrowB[k0 + 8 + fk];
                mma16816(c0, c1, c2, c3, a0, 0u, a2, 0u, b0, b1);
            }
            float* p = pbuf + (cgB * 8 + ksB) * 64;
            p[frow * 8 + fk]     = c0;
            p[frow * 8 + fk + 1] = c1;
        }
        __syncthreads();

        // reduce + update: tid<128 -> (b, c)
        if (tid < 128) {
            int b = tid >> 4, c = tid & 15;
            int cg = c >> 3, j = c & 7;
            float s = 0.f;
#pragma unroll
            for (int ks = 0; ks < 8; ks++)
                s += pbuf[(cg * 8 + ks) * 64 + b * 8 + j];
            float hbar  = tanhf(s + xbuf[b * 48 + 32 + c] + bsm[32 + c]);
            float hprev = hpsm[tid];
            float z     = zsm[tid];
            float hn    = hprev + z * (hbar - hprev);
            hpsm[tid] = hn;
            __half hh = __float2half(hn);
            int cc = colbase + c;
            g_h16[b * NHID + cc] = hh;
            g_hs[(size_t)(b * TSTEPS + t) * NHID + cc] = hh;
        }
        group_barrier(&g_ctrs[128]);
    }
}

// ---------------------------------------------------------------------------
// Prep kernels
// ---------------------------------------------------------------------------
__global__ void cvt_half2(const float2* __restrict__ src, __half2* __restrict__ dst, int n2) {
    int i = blockIdx.x * blockDim.x + threadIdx.x;
    int stride = gridDim.x * blockDim.x;
    for (; i < n2; i += stride) {
        float2 v = src[i];
        dst[i] = __floats2half2_rn(v.x, v.y);
    }
}

__global__ void build_wx(const float* __restrict__ Wz, const float* __restrict__ Wr,
                         const float* __restrict__ Wh, __half* __restrict__ dst) {
    int i = blockIdx.x * blockDim.x + threadIdx.x;
    if (i >= NEMBD * NG3) return;
    int k = i / NG3, c = i - k * NG3;
    int g = c >> 10, j = c & 1023;
    const float* W = (g == 0) ? Wz : ((g == 1) ? Wr : Wh);
    dst[i] = __float2half(W[(size_t)k * NHID + j]);
}

__global__ void gather_emb(const int* __restrict__ idx, const float* __restrict__ wte,
                           __half* __restrict__ dst) {
    int r = blockIdx.x;
    int tok = idx[r];
    float4 v = ((const float4*)(wte + (size_t)tok * NEMBD))[threadIdx.x];
    __half2* d = (__half2*)(dst + (size_t)r * NEMBD);
    d[threadIdx.x * 2]     = __floats2half2_rn(v.x, v.y);
    d[threadIdx.x * 2 + 1] = __floats2half2_rn(v.z, v.w);
}

// ---------------------------------------------------------------------------
// fp16 tensor-core GEMM: C[M,NCOLS] = A[M,KDIM] * B[KDIM,NCOLS] (+bias)
// ---------------------------------------------------------------------------
#define AS_STRIDE 40
#define BS_STRIDE 42

template<int KDIM, int NCOLS2, bool HAS_BIAS>
__global__ void __launch_bounds__(256)
gemm_kernel(const __half* __restrict__ A, const __half* __restrict__ Bw,
            const float* __restrict__ bias, float* __restrict__ C) {
    const int bx = blockIdx.x, by = blockIdx.y;
    const int tid = threadIdx.x, warp = tid >> 5, lane = tid & 31;
    const int wm = warp >> 2, wn = warp & 3;
    __shared__ __half As[128 * AS_STRIDE];
    __shared__ __half Bs[128 * BS_STRIDE];

    float acc[4][4][4];
#pragma unroll
    for (int a = 0; a < 4; a++)
#pragma unroll
        for (int b = 0; b < 4; b++)
#pragma unroll
            for (int c = 0; c < 4; c++) acc[a][b][c] = 0.f;

    const int m0 = by * 128, n0 = bx * 128;

    for (int k0 = 0; k0 < KDIM; k0 += 32) {
#pragma unroll
        for (int i = tid; i < 512; i += 256) {
            int row = i >> 2, seg = i & 3;
            *(uint4*)&As[row * AS_STRIDE + seg * 8] =
                *(const uint4*)&A[(size_t)(m0 + row) * KDIM + k0 + seg * 8];
        }
#pragma unroll
        for (int i = tid; i < 2048; i += 256) {
            int k = i >> 6, np = i & 63;
            __half2 h2 = *(const __half2*)(Bw + (size_t)(k0 + k) * NCOLS2 + n0 + np * 2);
            Bs[(np * 2)     * BS_STRIDE + k] = __low2half(h2);
            Bs[(np * 2 + 1) * BS_STRIDE + k] = __high2half(h2);
        }
        __syncthreads();

#pragma unroll
        for (int kk = 0; kk < 2; kk++) {
            unsigned a[4][4], b[4][2];
            const int kc = kk * 16 + (lane & 3) * 2;
            const int r  = lane >> 2;
#pragma unroll
            for (int mt = 0; mt < 4; mt++) {
                int rr = wm * 64 + mt * 16 + r;
                a[mt][0] = *(const unsigned*)&As[rr * AS_STRIDE + kc];
                a[mt][1] = *(const unsigned*)&As[(rr + 8) * AS_STRIDE + kc];
                a[mt][2] = *(const unsigned*)&As[rr * AS_STRIDE + kc + 8];
                a[mt][3] = *(const unsigned*)&As[(rr + 8) * AS_STRIDE + kc + 8];
            }
#pragma unroll
            for (int nt = 0; nt < 4; nt++) {
                int nn = wn * 32 + nt * 8 + r;
                b[nt][0] = *(const unsigned*)&Bs[nn * BS_STRIDE + kc];
                b[nt][1] = *(const unsigned*)&Bs[nn * BS_STRIDE + kc + 8];
            }
#pragma unroll
            for (int mt = 0; mt < 4; mt++)
#pragma unroll
                for (int nt = 0; nt < 4; nt++)
                    mma16816(acc[mt][nt][0], acc[mt][nt][1], acc[mt][nt][2], acc[mt][nt][3],
                             a[mt][0], a[mt][1], a[mt][2], a[mt][3], b[nt][0], b[nt][1]);
        }
        __syncthreads();
    }

#pragma unroll
    for (int mt = 0; mt < 4; mt++) {
#pragma unroll
        for (int nt = 0; nt < 4; nt++) {
            int gr = m0 + wm * 64 + mt * 16 + (lane >> 2);
            int gc = n0 + wn * 32 + nt * 8 + (lane & 3) * 2;
            float b0 = 0.f, b1 = 0.f;
            if (HAS_BIAS) { b0 = bias[gc]; b1 = bias[gc + 1]; }
            float2 v0 = make_float2(acc[mt][nt][0] + b0, acc[mt][nt][1] + b1);
            float2 v1 = make_float2(acc[mt][nt][2] + b0, acc[mt][nt][3] + b1);
            *(float2*)&C[(size_t)gr * NCOLS2 + gc]       = v0;
            *(float2*)&C[(size_t)(gr + 8) * NCOLS2 + gc] = v1;
        }
    }
}

// ---------------------------------------------------------------------------
// Loss
// ---------------------------------------------------------------------------
__global__ void __launch_bounds__(256)
loss_kernel(const float* __restrict__ logits, const int* __restrict__ targets,
            float* __restrict__ out_loss) {
    const int row = blockIdx.x;
    const float* lr = logits + (size_t)row * VOCAB;
    const int tid = threadIdx.x;

    float m = -1e30f, s = 0.f;
    for (int i = tid; i < VOCAB; i += 256) {
        float v = lr[i];
        float nm = fmaxf(m, v);
        s = s * __expf(m - nm) + __expf(v - nm);
        m = nm;
    }
    __shared__ float sm_m[256], sm_s[256];
    sm_m[tid] = m; sm_s[tid] = s;
    __syncthreads();
    for (int off = 128; off > 0; off >>= 1) {
        if (tid < off) {
            float m2 = sm_m[tid + off], s2 = sm_s[tid + off];
            float m1 = sm_m[tid],       s1 = sm_s[tid];
            float nm = fmaxf(m1, m2);
            sm_s[tid] = s1 * __expf(m1 - nm) + s2 * __expf(m2 - nm);
            sm_m[tid] = nm;
        }
        __syncthreads();
    }
    if (tid == 0) {
        float lse = sm_m[0] + logf(sm_s[0]);
        float tl  = lr[targets[row]];
        atomicAdd(out_loss, (lse - tl) * (1.0f / (float)NROWS));
    }
}

// ---------------------------------------------------------------------------
// Host entry
// ---------------------------------------------------------------------------
extern "C" void kernel_launch(void* const* d_in, const int* in_sizes, int n_in,
                              void* d_out, int out_size) {
    const int*   idx   = (const int*)d_in[0];
    const int*   tgt   = (const int*)d_in[1];
    const float* wte   = (const float*)d_in[2];
    const float* start = (const float*)d_in[3];
    const float* Wz    = (const float*)d_in[4];
    const float* bz    = (const float*)d_in[5];
    const float* Wr    = (const float*)d_in[6];
    const float* br    = (const float*)d_in[7];
    const float* Wh    = (const float*)d_in[8];
    const float* bh    = (const float*)d_in[9];
    const float* lmW   = (const float*)d_in[10];
    const float* lmb   = (const float*)d_in[11];

    void *p_hs, *p_wlm, *p_fb, *p_emb, *p_wx, *p_xp;
    cudaGetSymbolAddress(&p_hs,  g_hs);
    cudaGetSymbolAddress(&p_wlm, g_wlm);
    cudaGetSymbolAddress(&p_fb,  g_logits_fb);
    cudaGetSymbolAddress(&p_emb, g_emb);
    cudaGetSymbolAddress(&p_wx,  g_wx);
    cudaGetSymbolAddress(&p_xp,  g_xp);
    __half* d_hs  = (__half*)p_hs;
    __half* d_wlm = (__half*)p_wlm;
    float*  d_fb  = (float*)p_fb;
    __half* d_emb = (__half*)p_emb;
    __half* d_wx  = (__half*)p_wx;
    float*  d_xp  = (float*)p_xp;

    cudaFuncSetAttribute(gru_kernel, cudaFuncAttributeMaxDynamicSharedMemorySize,
                         GRU_SMEM_BYTES);

    build_wx<<<(NEMBD * NG3 + 255) / 256, 256>>>(Wz, Wr, Wh, d_wx);
    gather_emb<<<NROWS, 128>>>(idx, wte, d_emb);

    gemm_kernel<NEMBD, NG3, false><<<dim3(NG3 / 128, NROWS / 128), 256>>>(
        d_emb, d_wx, nullptr, d_xp);

    gru_kernel<<<GRU_BLOCKS, GRU_THREADS, GRU_SMEM_BYTES>>>(start, Wz, bz, Wr, br, Wh, bh);

    cvt_half2<<<4096, 256>>>((const float2*)lmW, (__half2*)d_wlm, (NHID * VOCAB) / 2);
    const long long NL = (long long)NROWS * VOCAB;
    float* fo = (float*)d_out;
    float* logits = ((long long)out_size >= NL) ? fo : d_fb;
    gemm_kernel<NHID, VOCAB, true><<<dim3(VOCAB / 128, NROWS / 128), 256>>>(
        d_hs, d_wlm, lmb, logits);

    float* loss_ptr = nullptr;
    if ((long long)out_size >= NL + 1)      loss_ptr = fo + NL;
    else if ((long long)out_size < NL)      loss_ptr = fo;
    if (loss_ptr) {
        cudaMemsetAsync(loss_ptr, 0, sizeof(float));
        loss_kernel<<<NROWS, 256>>>(logits, tgt, loss_ptr);
    }
}